// round 13
// baseline (speedup 1.0000x reference)
#include <cuda_runtime.h>
#include <math.h>

#define NN  10000
#define NE  160000
#define TT  12
#define FIN 32
#define HH  64

typedef unsigned long long ull;

// ---------- packed f32x2 helpers ----------
__device__ __forceinline__ ull ffma2(ull a, ull b, ull c){
    ull d; asm("fma.rn.f32x2 %0, %1, %2, %3;" : "=l"(d) : "l"(a), "l"(b), "l"(c)); return d;
}
__device__ __forceinline__ ull pack2(float lo, float hi){
    ull r; asm("mov.b64 %0, {%1, %2};" : "=l"(r) : "f"(lo), "f"(hi)); return r;
}
__device__ __forceinline__ void unpack2(ull v, float& lo, float& hi){
    asm("mov.b64 {%0, %1}, %2;" : "=f"(lo), "=f"(hi) : "l"(v));
}
__device__ __forceinline__ float tanha(float x){
    float y; asm("tanh.approx.f32 %0, %1;" : "=f"(y) : "f"(x)); return y;
}
__device__ __forceinline__ float fsig(float x){ return 0.5f * tanha(0.5f * x) + 0.5f; }
__device__ __forceinline__ void barsync256(){
    asm volatile("bar.sync 0, 256;" ::: "memory");
}

__device__ int   g_is64;
__device__ int   g_cnt[NN];
__device__ int   g_off[NN];
__device__ int   g_cur[NN];
__device__ int   g_src[NE];
__device__ int   g_bsum[80];
__device__ float g_dis[NN];
__device__ float g_h0  [NN * TT * HH];
__device__ float g_agg1[NN * TT * HH];
__device__ float g_hs0 [NN * TT * HH];
__device__ float g_pre [NN * TT * 256];     // float4 layout: [row][hcol]{i,f,g,o}

// ---------- CSR build ----------
__global__ void k_init(const int* __restrict__ w){
    int i = blockIdx.x * blockDim.x + threadIdx.x;
    if (i < NN) g_cnt[i] = 0;
    if (blockIdx.x == 0 && threadIdx.x == 0){
        int any = 0;
        #pragma unroll
        for (int j = 1; j < 129; j += 2) any |= w[j];
        g_is64 = (any == 0) ? 1 : 0;
    }
}

__global__ void k_count(const void* __restrict__ ei){
    int e = blockIdx.x * blockDim.x + threadIdx.x;
    if (e >= NE) return;
    int c = g_is64 ? (int)((const long long*)ei)[NE + e]
                   : ((const int*)ei)[NE + e];
    atomicAdd(&g_cnt[c], 1);
}

__global__ void k_scan1(){
    int b = blockIdx.x, t = threadIdx.x;
    int i = b * 128 + t;
    int v = (i < NN) ? g_cnt[i] : 0;
    int lane = t & 31, w = t >> 5;
    int s = v;
    #pragma unroll
    for (int d = 16; d > 0; d >>= 1) s += __shfl_down_sync(0xffffffffu, s, d);
    __shared__ int ws[4];
    if (lane == 0) ws[w] = s;
    __syncthreads();
    if (t == 0) g_bsum[b] = ws[0] + ws[1] + ws[2] + ws[3];
}

__global__ void k_scan3(){
    int b = blockIdx.x, t = threadIdx.x;
    __shared__ int sbase;
    __shared__ int ws[4];
    if (t < 32){
        int s = 0;
        for (int i = t; i < b; i += 32) s += g_bsum[i];
        #pragma unroll
        for (int d = 16; d > 0; d >>= 1) s += __shfl_down_sync(0xffffffffu, s, d);
        if (t == 0) sbase = s;
    }
    int i = b * 128 + t;
    int v = (i < NN) ? g_cnt[i] : 0;
    int lane = t & 31, w = t >> 5;
    int incl = v;
    #pragma unroll
    for (int d = 1; d < 32; d <<= 1){
        int o = __shfl_up_sync(0xffffffffu, incl, d);
        if (lane >= d) incl += o;
    }
    if (lane == 31) ws[w] = incl;
    __syncthreads();
    int base = sbase;
    for (int k = 0; k < w; ++k) base += ws[k];
    if (i < NN){
        g_off[i] = base + incl - v;
        g_cur[i] = 0;
        g_dis[i] = rsqrtf((float)(v + 1));
    }
}

__global__ void k_fill(const void* __restrict__ ei){
    int e = blockIdx.x * blockDim.x + threadIdx.x;
    if (e >= NE) return;
    int r, c;
    if (g_is64){
        r = (int)((const long long*)ei)[e];
        c = (int)((const long long*)ei)[NE + e];
    } else {
        r = ((const int*)ei)[e];
        c = ((const int*)ei)[NE + e];
    }
    int p = atomicAdd(&g_cur[c], 1);
    g_src[g_off[c] + p] = r;
}

// ---------- fused: aggregate raw x + GCN layer-0 GEMM + relu -> g_h0 ----------
__global__ __launch_bounds__(128)
void k_aggx_gcn0(const float* __restrict__ x, const float* __restrict__ W,
                 const float* __restrict__ bvec){
    __shared__ float s_ag[12 * 33];
    __shared__ float W_s[32 * 64];
    __shared__ float b_s[64];
    int c   = blockIdx.x;
    int off = g_off[c], len = g_cnt[c];
    float dc = g_dis[c];
    int t = threadIdx.x;

    for (int idx = t; idx < 2048; idx += 128) W_s[idx] = W[idx];
    if (t < 64) b_s[t] = bvec[t];

    int p0 = t, p1 = t + 128, p2 = t + 256;
    int b0 = (p0 >> 5) * (NN * FIN) + (p0 & 31);
    int b1 = (p1 >> 5) * (NN * FIN) + (p1 & 31);
    int b2 = (p2 >> 5) * (NN * FIN) + (p2 & 31);
    int cb = c * FIN;
    float a0 = dc * x[b0 + cb];
    float a1 = dc * x[b1 + cb];
    float a2 = dc * x[b2 + cb];
    for (int e = 0; e < len; ++e){
        int r = g_src[off + e];
        float dr = g_dis[r];
        int rb = r * FIN;
        a0 += dr * x[b0 + rb];
        a1 += dr * x[b1 + rb];
        a2 += dr * x[b2 + rb];
    }
    s_ag[(p0 >> 5) * 33 + (p0 & 31)] = dc * a0;
    s_ag[(p1 >> 5) * 33 + (p1 & 31)] = dc * a1;
    s_ag[(p2 >> 5) * 33 + (p2 & 31)] = dc * a2;
    __syncthreads();

    int col = t & 63;
    int Tb  = t >> 6;
    float acc[6];
    #pragma unroll
    for (int q = 0; q < 6; ++q) acc[q] = b_s[col];
    #pragma unroll 8
    for (int f = 0; f < 32; ++f){
        float w = W_s[f * 64 + col];
        #pragma unroll
        for (int q = 0; q < 6; ++q)
            acc[q] += s_ag[(Tb + 2 * q) * 33 + f] * w;
    }
    #pragma unroll
    for (int q = 0; q < 6; ++q)
        g_h0[(c * TT + Tb + 2 * q) * 64 + col] = fmaxf(acc[q], 0.f);
}

// ---------- aggregate h0 (N,T,64) -> (N,T,64) ----------
__global__ void k_agg_h(){
    int c   = blockIdx.x;
    int off = g_off[c], len = g_cnt[c];
    float dc = g_dis[c];
    int t = threadIdx.x;
    int cb = c * 768;
    float a0 = dc * g_h0[cb + t];
    float a1 = dc * g_h0[cb + t + 256];
    float a2 = dc * g_h0[cb + t + 512];
    for (int e = 0; e < len; ++e){
        int r = g_src[off + e];
        float dr = g_dis[r];
        int rb = r * 768;
        a0 += dr * g_h0[rb + t];
        a1 += dr * g_h0[rb + t + 256];
        a2 += dr * g_h0[rb + t + 512];
    }
    g_agg1[cb + t]       = dc * a0;
    g_agg1[cb + t + 256] = dc * a1;
    g_agg1[cb + t + 512] = dc * a2;
}

// ---------- fused GCN layer 1 (FFMA2) + LSTM-0 input projection ----------
#define GX_SMEM (25152 * 4)
__global__ __launch_bounds__(256)
void k_gcn1x(const float* __restrict__ W1, const float* __restrict__ b1,
             const float* __restrict__ wih, const float* __restrict__ bih,
             const float* __restrict__ bhh){
    extern __shared__ float sm[];
    float* A_s  = sm;             // 64 x 98  (agg1 tile, [k][n])
    float* W1_s = sm + 6272;      // 64 x 64
    float* b1_s = sm + 10368;     // 64
    float* A2_s = sm + 10432;     // 64 x 98  (h1 tile, [col][n])
    float* Wi_s = sm + 16704;     // 128 x 65
    float* bb_s = sm + 25024;     // 128
    int t  = threadIdx.x;
    int nb = blockIdx.x * 96;
    int jj = t & 31, pg = t >> 5;

    for (int idx = t; idx < 4096; idx += 256) W1_s[idx] = W1[idx];
    if (t < 64) b1_s[t] = b1[t];
    for (int idx = t; idx < 96 * 64; idx += 256){
        int n = idx >> 6, k = idx & 63;
        A_s[k * 98 + n] = g_agg1[(nb + n) * 64 + k];
    }
    __syncthreads();

    {   // GEMM1: 96 x 64
        ull acc[6][2];
        #pragma unroll
        for (int p = 0; p < 6; ++p){ acc[p][0] = 0ull; acc[p][1] = 0ull; }
        #pragma unroll 8
        for (int k = 0; k < 64; ++k){
            float w0 = W1_s[k * 64 + jj], w1 = W1_s[k * 64 + jj + 32];
            ull W0 = pack2(w0, w0), W1v = pack2(w1, w1);
            const float* Ar = &A_s[k * 98 + pg * 12];
            #pragma unroll
            for (int p = 0; p < 6; ++p){
                ull a = *(const ull*)(Ar + 2 * p);
                acc[p][0] = ffma2(a, W0, acc[p][0]);
                acc[p][1] = ffma2(a, W1v, acc[p][1]);
            }
        }
        float bb0 = b1_s[jj], bb1 = b1_s[jj + 32];
        #pragma unroll
        for (int p = 0; p < 6; ++p){
            float v0l, v0h, v1l, v1h;
            unpack2(acc[p][0], v0l, v0h);
            unpack2(acc[p][1], v1l, v1h);
            int n0 = pg * 12 + 2 * p;
            A2_s[jj * 98 + n0]            = fmaxf(v0l + bb0, 0.f);
            A2_s[jj * 98 + n0 + 1]        = fmaxf(v0h + bb0, 0.f);
            A2_s[(jj + 32) * 98 + n0]     = fmaxf(v1l + bb1, 0.f);
            A2_s[(jj + 32) * 98 + n0 + 1] = fmaxf(v1h + bb1, 0.f);
        }
    }
    __syncthreads();

    for (int half = 0; half < 2; ++half){
        for (int idx = t; idx < 128 * 64; idx += 256){
            int r = idx >> 6, k = idx & 63;
            int grow = (r >> 5) * 64 + half * 32 + (r & 31);
            Wi_s[r * 65 + k] = wih[grow * 64 + k];
        }
        if (t < 128){
            int grow = (t >> 5) * 64 + half * 32 + (t & 31);
            bb_s[t] = bih[grow] + bhh[grow];
        }
        __syncthreads();

        ull acc2[6][4];
        #pragma unroll
        for (int p = 0; p < 6; ++p)
            #pragma unroll
            for (int g = 0; g < 4; ++g) acc2[p][g] = 0ull;

        #pragma unroll 4
        for (int k = 0; k < 64; ++k){
            const float* Ar = &A2_s[k * 98 + pg * 12];
            ull a0 = *(const ull*)(Ar + 0);
            ull a1 = *(const ull*)(Ar + 2);
            ull a2 = *(const ull*)(Ar + 4);
            ull a3 = *(const ull*)(Ar + 6);
            ull a4 = *(const ull*)(Ar + 8);
            ull a5 = *(const ull*)(Ar + 10);
            #pragma unroll
            for (int g = 0; g < 4; ++g){
                float w = Wi_s[(g * 32 + jj) * 65 + k];
                ull W2 = pack2(w, w);
                acc2[0][g] = ffma2(a0, W2, acc2[0][g]);
                acc2[1][g] = ffma2(a1, W2, acc2[1][g]);
                acc2[2][g] = ffma2(a2, W2, acc2[2][g]);
                acc2[3][g] = ffma2(a3, W2, acc2[3][g]);
                acc2[4][g] = ffma2(a4, W2, acc2[4][g]);
                acc2[5][g] = ffma2(a5, W2, acc2[5][g]);
            }
        }
        float bi = bb_s[jj], bf = bb_s[32 + jj], bg = bb_s[64 + jj], bo = bb_s[96 + jj];
        int hcol = half * 32 + jj;
        #pragma unroll
        for (int p = 0; p < 6; ++p){
            float i0, i1, f0, f1, g0, g1, o0, o1;
            unpack2(acc2[p][0], i0, i1);
            unpack2(acc2[p][1], f0, f1);
            unpack2(acc2[p][2], g0, g1);
            unpack2(acc2[p][3], o0, o1);
            int row = nb + pg * 12 + 2 * p;
            ((float4*)g_pre)[row * 64 + hcol]       = make_float4(i0 + bi, f0 + bf, g0 + bg, o0 + bo);
            ((float4*)g_pre)[(row + 1) * 64 + hcol] = make_float4(i1 + bi, f1 + bf, g1 + bg, o1 + bo);
        }
        __syncthreads();
    }
}

// ---------- LSTM-1 input projection (single pass, all 256 cols) ----------
// smem: A 64x98 | Wi 256x65 | bias 256  = 23168 floats (92.7 KB) -> 2 blocks/SM
#define XP_SMEM ((6272 + 16640 + 256) * 4)
__global__ __launch_bounds__(256)
void k_xproj2(const float* __restrict__ wih, const float* __restrict__ bih,
              const float* __restrict__ bhh){
    extern __shared__ float sm[];
    float* A_s  = sm;            // 64 x 98  [k][n]
    float* Wi_s = sm + 6272;     // 256 x 65 [gate-row][k]
    float* bb_s = sm + 6272 + 16640;
    int t  = threadIdx.x;
    int nb = blockIdx.x * 96;
    int jj = t & 31, pg = t >> 5;

    for (int idx = t; idx < 256 * 64; idx += 256){
        int r = idx >> 6, k = idx & 63;
        Wi_s[r * 65 + k] = wih[r * 64 + k];
    }
    bb_s[t] = bih[t] + bhh[t];
    for (int idx = t; idx < 96 * 64; idx += 256){
        int n = idx >> 6, k = idx & 63;
        A_s[k * 98 + n] = g_hs0[(nb + n) * 64 + k];
    }
    __syncthreads();

    ull acc2[6][4][2];
    #pragma unroll
    for (int p = 0; p < 6; ++p)
        #pragma unroll
        for (int g = 0; g < 4; ++g){ acc2[p][g][0] = 0ull; acc2[p][g][1] = 0ull; }

    #pragma unroll 4
    for (int k = 0; k < 64; ++k){
        const float* Ar = &A_s[k * 98 + pg * 12];
        ull a0 = *(const ull*)(Ar + 0);
        ull a1 = *(const ull*)(Ar + 2);
        ull a2 = *(const ull*)(Ar + 4);
        ull a3 = *(const ull*)(Ar + 6);
        ull a4 = *(const ull*)(Ar + 8);
        ull a5 = *(const ull*)(Ar + 10);
        #pragma unroll
        for (int g = 0; g < 4; ++g){
            #pragma unroll
            for (int hs = 0; hs < 2; ++hs){
                float w = Wi_s[(g * 64 + jj + 32 * hs) * 65 + k];
                ull W2 = pack2(w, w);
                acc2[0][g][hs] = ffma2(a0, W2, acc2[0][g][hs]);
                acc2[1][g][hs] = ffma2(a1, W2, acc2[1][g][hs]);
                acc2[2][g][hs] = ffma2(a2, W2, acc2[2][g][hs]);
                acc2[3][g][hs] = ffma2(a3, W2, acc2[3][g][hs]);
                acc2[4][g][hs] = ffma2(a4, W2, acc2[4][g][hs]);
                acc2[5][g][hs] = ffma2(a5, W2, acc2[5][g][hs]);
            }
        }
    }
    #pragma unroll
    for (int hs = 0; hs < 2; ++hs){
        int hcol = jj + 32 * hs;
        float bi = bb_s[hcol], bf = bb_s[64 + hcol], bg = bb_s[128 + hcol], bo = bb_s[192 + hcol];
        #pragma unroll
        for (int p = 0; p < 6; ++p){
            float i0, i1, f0, f1, g0, g1, o0, o1;
            unpack2(acc2[p][0][hs], i0, i1);
            unpack2(acc2[p][1][hs], f0, f1);
            unpack2(acc2[p][2][hs], g0, g1);
            unpack2(acc2[p][3][hs], o0, o1);
            int row = nb + pg * 12 + 2 * p;
            ((float4*)g_pre)[row * 64 + hcol]       = make_float4(i0 + bi, f0 + bf, g0 + bg, o0 + bo);
            ((float4*)g_pre)[(row + 1) * 64 + hcol] = make_float4(i1 + bi, f1 + bf, g1 + bg, o1 + bo);
        }
    }
}

// ---------- persistent per-layer LSTM: 148 blocks, 66/68 nodes each ----------
// pairs: 5000 total; blocks 0..115 -> 34 pairs, 116..147 -> 33 pairs.
// Within a block, warps 0..r-1 carry 5 pairs (r = npairs-32), rest 4 —
// the heavy warps land in different SMSPs (wid 0,1). Inner loop templated
// on NP with warp-uniform divergence + arrival-counted bar.sync.
#define LSTM_SMEM ((256 * 65 + 64 * 82 + 64 * 82) * 4)

template<int NP>
__device__ __forceinline__ void lstm_run(int layer, const float* __restrict__ W_s,
                                         float* __restrict__ h_s, float* __restrict__ c_s,
                                         int nodeBase, int nOff, int jj){
    for (int st = 0; st < TT; ++st){
        float4 pv[NP][2][2];
        #pragma unroll
        for (int p = 0; p < NP; ++p)
            #pragma unroll
            for (int hs2 = 0; hs2 < 2; ++hs2)
                #pragma unroll
                for (int half = 0; half < 2; ++half){
                    int nloc = nOff + 2 * p + half;
                    int hcol = jj + 32 * hs2;
                    pv[p][hs2][half] =
                        ((const float4*)g_pre)[((nodeBase + nloc) * TT + st) * 64 + hcol];
                }

        ull acc[8][NP];
        #pragma unroll
        for (int g = 0; g < 8; ++g)
            #pragma unroll
            for (int p = 0; p < NP; ++p) acc[g][p] = 0ull;

        #pragma unroll 4
        for (int kk = 0; kk < 64; ++kk){
            const float* Ar = h_s + kk * 82 + nOff;
            ull a[NP];
            #pragma unroll
            for (int p = 0; p < NP; ++p) a[p] = *(const ull*)(Ar + 2 * p);
            #pragma unroll
            for (int g = 0; g < 8; ++g){
                float w = W_s[(jj + 32 * g) * 65 + kk];
                ull W2 = pack2(w, w);
                #pragma unroll
                for (int p = 0; p < NP; ++p) acc[g][p] = ffma2(a[p], W2, acc[g][p]);
            }
        }
        barsync256();                      // all h_s reads done

        #pragma unroll
        for (int p = 0; p < NP; ++p){
            #pragma unroll
            for (int hs2 = 0; hs2 < 2; ++hs2){
                int hcol = jj + 32 * hs2;
                float i0, i1, f0, f1, g0, g1, o0, o1;
                unpack2(acc[0 + hs2][p], i0, i1);
                unpack2(acc[2 + hs2][p], f0, f1);
                unpack2(acc[4 + hs2][p], g0, g1);
                unpack2(acc[6 + hs2][p], o0, o1);
                #pragma unroll
                for (int half = 0; half < 2; ++half){
                    int nloc = nOff + 2 * p + half;
                    float4 pvv = pv[p][hs2][half];
                    float iv = (half ? i1 : i0) + pvv.x;
                    float fv = (half ? f1 : f0) + pvv.y;
                    float gv = (half ? g1 : g0) + pvv.z;
                    float ov = (half ? o1 : o0) + pvv.w;
                    float cold = c_s[hcol * 82 + nloc];
                    float cn = fsig(fv) * cold + fsig(iv) * tanha(gv);
                    float hn = fsig(ov) * tanha(cn);
                    c_s[hcol * 82 + nloc] = cn;
                    h_s[hcol * 82 + nloc] = hn;
                    if (layer == 0)
                        g_hs0[((nodeBase + nloc) * TT + st) * 64 + hcol] = hn;
                }
            }
        }
        barsync256();                      // h_s fully updated
    }
}

__global__ __launch_bounds__(256, 1)
void k_lstm_layer(int layer, const float* __restrict__ whh,
                  const float* __restrict__ fcw, const float* __restrict__ fcb,
                  float* __restrict__ out){
    extern __shared__ float smem[];
    float* W_s = smem;                 // [c 0..255][kk 0..63], pitch 65
    float* h_s = smem + 256 * 65;      // [hcol 0..63][nloc], pitch 82
    float* c_s = h_s + 64 * 82;

    int t  = threadIdx.x;
    int jj = t & 31, wg = t >> 5;
    int b  = blockIdx.x;
    int pairBase = b * 33 + min(b, 116);
    int npairs   = (b < 116) ? 34 : 33;
    int nodeBase = 2 * pairBase;
    int nNodes   = 2 * npairs;
    int r        = npairs - 32;                    // 1 or 2
    int wpairs   = 4 + (wg < r ? 1 : 0);
    int nOff     = 2 * (4 * wg + min(wg, r));      // local node offset (even)

    for (int idx = t; idx < 256 * 64; idx += 256){
        int k = idx & 63, c = idx >> 6;
        W_s[c * 65 + k] = whh[idx];
    }
    for (int idx = t; idx < 64 * 82; idx += 256){
        h_s[idx] = 0.f;
        c_s[idx] = 0.f;
    }
    __syncthreads();

    if (wpairs == 5) lstm_run<5>(layer, W_s, h_s, c_s, nodeBase, nOff, jj);
    else             lstm_run<4>(layer, W_s, h_s, c_s, nodeBase, nOff, jj);

    if (layer == 1){
        __syncthreads();
        for (int idx = t; idx < 1024; idx += 256){
            int k = idx >> 4, o = idx & 15;
            W_s[k * 16 + o] = fcw[o * 64 + k];
        }
        __syncthreads();
        for (int oi = t; oi < nNodes * 16; oi += 256){
            int nloc = oi >> 4, o = oi & 15;
            float acc = fcb[o];
            #pragma unroll 8
            for (int k = 0; k < 64; ++k)
                acc += h_s[k * 82 + nloc] * W_s[k * 16 + o];
            out[(nodeBase + nloc) * 16 + o] = acc;
        }
    }
}

extern "C" void kernel_launch(void* const* d_in, const int* in_sizes, int n_in,
                              void* d_out, int out_size){
    const float* x    = (const float*)d_in[0];
    const void*  ei   =               d_in[1];
    const float* gw0  = (const float*)d_in[2];
    const float* gb0  = (const float*)d_in[3];
    const float* gw1  = (const float*)d_in[4];
    const float* gb1  = (const float*)d_in[5];
    const float* wih0 = (const float*)d_in[6];
    const float* whh0 = (const float*)d_in[7];
    const float* bih0 = (const float*)d_in[8];
    const float* bhh0 = (const float*)d_in[9];
    const float* wih1 = (const float*)d_in[10];
    const float* whh1 = (const float*)d_in[11];
    const float* bih1 = (const float*)d_in[12];
    const float* bhh1 = (const float*)d_in[13];
    const float* fcw  = (const float*)d_in[14];
    const float* fcb  = (const float*)d_in[15];
    float* out = (float*)d_out;

    cudaFuncSetAttribute(k_lstm_layer, cudaFuncAttributeMaxDynamicSharedMemorySize, LSTM_SMEM);
    cudaFuncSetAttribute(k_gcn1x,      cudaFuncAttributeMaxDynamicSharedMemorySize, GX_SMEM);
    cudaFuncSetAttribute(k_xproj2,     cudaFuncAttributeMaxDynamicSharedMemorySize, XP_SMEM);

    // CSR build
    k_init <<<40, 256>>>((const int*)ei);
    k_count<<<(NE + 255) / 256, 256>>>(ei);
    k_scan1<<<79, 128>>>();
    k_scan3<<<79, 128>>>();
    k_fill <<<(NE + 255) / 256, 256>>>(ei);

    // GCN layer 0 (aggregation + GEMM fused)
    k_aggx_gcn0<<<NN, 128>>>(x, gw0, gb0);
    // GCN layer 1 fused with LSTM-0 input projection
    k_agg_h<<<NN, 256>>>();
    k_gcn1x<<<1250, 256, GX_SMEM>>>(gw1, gb1, wih0, bih0, bhh0);

    // LSTM layer 0
    k_lstm_layer<<<148, 256, LSTM_SMEM>>>(0, whh0, fcw, fcb, out);

    // LSTM layer 1 (single-pass input projection; FC fused into epilogue)
    k_xproj2<<<1250, 256, XP_SMEM>>>(wih1, bih1, bhh1);
    k_lstm_layer<<<148, 256, LSTM_SMEM>>>(1, whh1, fcw, fcb, out);
}

// round 14
// speedup vs baseline: 1.0986x; 1.0986x over previous
#include <cuda_runtime.h>
#include <math.h>

#define NN  10000
#define NE  160000
#define TT  12
#define FIN 32
#define HH  64

typedef unsigned long long ull;

// ---------- packed f32x2 helpers ----------
__device__ __forceinline__ ull ffma2(ull a, ull b, ull c){
    ull d; asm("fma.rn.f32x2 %0, %1, %2, %3;" : "=l"(d) : "l"(a), "l"(b), "l"(c)); return d;
}
__device__ __forceinline__ ull pack2(float lo, float hi){
    ull r; asm("mov.b64 %0, {%1, %2};" : "=l"(r) : "f"(lo), "f"(hi)); return r;
}
__device__ __forceinline__ void unpack2(ull v, float& lo, float& hi){
    asm("mov.b64 {%0, %1}, %2;" : "=f"(lo), "=f"(hi) : "l"(v));
}
__device__ __forceinline__ float tanha(float x){
    float y; asm("tanh.approx.f32 %0, %1;" : "=f"(y) : "f"(x)); return y;
}
__device__ __forceinline__ float fsig(float x){ return 0.5f * tanha(0.5f * x) + 0.5f; }

__device__ int   g_is64;
__device__ int   g_cnt[NN];
__device__ int   g_off[NN];
__device__ int   g_cur[NN];
__device__ int   g_src[NE];
__device__ int   g_bsum[80];
__device__ float g_dis[NN];
__device__ float g_h0  [NN * TT * HH];
__device__ float g_agg1[NN * TT * HH];
__device__ float g_hs0 [NN * TT * HH];
__device__ float g_pre [NN * TT * 256];     // float4 layout: [row][hcol]{i,f,g,o}

// ---------- CSR build ----------
__global__ void k_init(const int* __restrict__ w){
    int i = blockIdx.x * blockDim.x + threadIdx.x;
    if (i < NN) g_cnt[i] = 0;
    if (blockIdx.x == 0 && threadIdx.x == 0){
        int any = 0;
        #pragma unroll
        for (int j = 1; j < 129; j += 2) any |= w[j];
        g_is64 = (any == 0) ? 1 : 0;
    }
}

__global__ void k_count(const void* __restrict__ ei){
    int e = blockIdx.x * blockDim.x + threadIdx.x;
    if (e >= NE) return;
    int c = g_is64 ? (int)((const long long*)ei)[NE + e]
                   : ((const int*)ei)[NE + e];
    atomicAdd(&g_cnt[c], 1);
}

__global__ void k_scan1(){
    int b = blockIdx.x, t = threadIdx.x;
    int i = b * 128 + t;
    int v = (i < NN) ? g_cnt[i] : 0;
    int lane = t & 31, w = t >> 5;
    int s = v;
    #pragma unroll
    for (int d = 16; d > 0; d >>= 1) s += __shfl_down_sync(0xffffffffu, s, d);
    __shared__ int ws[4];
    if (lane == 0) ws[w] = s;
    __syncthreads();
    if (t == 0) g_bsum[b] = ws[0] + ws[1] + ws[2] + ws[3];
}

__global__ void k_scan3(){
    int b = blockIdx.x, t = threadIdx.x;
    __shared__ int sbase;
    __shared__ int ws[4];
    if (t < 32){
        int s = 0;
        for (int i = t; i < b; i += 32) s += g_bsum[i];
        #pragma unroll
        for (int d = 16; d > 0; d >>= 1) s += __shfl_down_sync(0xffffffffu, s, d);
        if (t == 0) sbase = s;
    }
    int i = b * 128 + t;
    int v = (i < NN) ? g_cnt[i] : 0;
    int lane = t & 31, w = t >> 5;
    int incl = v;
    #pragma unroll
    for (int d = 1; d < 32; d <<= 1){
        int o = __shfl_up_sync(0xffffffffu, incl, d);
        if (lane >= d) incl += o;
    }
    if (lane == 31) ws[w] = incl;
    __syncthreads();
    int base = sbase;
    for (int k = 0; k < w; ++k) base += ws[k];
    if (i < NN){
        g_off[i] = base + incl - v;
        g_cur[i] = 0;
        g_dis[i] = rsqrtf((float)(v + 1));
    }
}

__global__ void k_fill(const void* __restrict__ ei){
    int e = blockIdx.x * blockDim.x + threadIdx.x;
    if (e >= NE) return;
    int r, c;
    if (g_is64){
        r = (int)((const long long*)ei)[e];
        c = (int)((const long long*)ei)[NE + e];
    } else {
        r = ((const int*)ei)[e];
        c = ((const int*)ei)[NE + e];
    }
    int p = atomicAdd(&g_cur[c], 1);
    g_src[g_off[c] + p] = r;
}

// ---------- fused: aggregate raw x + GCN layer-0 GEMM + relu -> g_h0 ----------
// 4 nodes per block (grid 2500): W0/b0 staged once per 4 nodes, 64 threads/node
// (2 warps per node -> warp-uniform edge loop).
__global__ __launch_bounds__(256)
void k_aggx_gcn0(const float* __restrict__ x, const float* __restrict__ W,
                 const float* __restrict__ bvec){
    __shared__ float s_ag[4][12 * 33];
    __shared__ float W_s[32 * 64];
    __shared__ float b_s[64];
    int t  = threadIdx.x;
    int ln = t >> 6;                 // local node 0..3
    int tt = t & 63;                 // 64 threads per node
    int c  = blockIdx.x * 4 + ln;

    for (int idx = t; idx < 2048; idx += 256) W_s[idx] = W[idx];
    if (t < 64) b_s[t] = bvec[t];

    int off = g_off[c], len = g_cnt[c];
    float dc = g_dis[c];

    // 6 positions per thread: p = tt + 64*q over 384 = 12*32
    int pb[6], pT[6];
    float a[6];
    #pragma unroll
    for (int q = 0; q < 6; ++q){
        int p = tt + 64 * q;
        pT[q] = p >> 5;
        pb[q] = (p >> 5) * (NN * FIN) + (p & 31);
    }
    int cb = c * FIN;
    #pragma unroll
    for (int q = 0; q < 6; ++q) a[q] = dc * x[pb[q] + cb];
    for (int e = 0; e < len; ++e){
        int r = g_src[off + e];
        float dr = g_dis[r];
        int rb = r * FIN;
        #pragma unroll
        for (int q = 0; q < 6; ++q) a[q] += dr * x[pb[q] + rb];
    }
    #pragma unroll
    for (int q = 0; q < 6; ++q){
        int p = tt + 64 * q;
        s_ag[ln][pT[q] * 33 + (p & 31)] = dc * a[q];
    }
    __syncthreads();

    // GEMM per node: 64 threads, thread tt -> col tt, all 12 T-rows
    int col = tt;
    float acc[12];
    #pragma unroll
    for (int T = 0; T < 12; ++T) acc[T] = b_s[col];
    #pragma unroll 8
    for (int f = 0; f < 32; ++f){
        float w = W_s[f * 64 + col];
        #pragma unroll
        for (int T = 0; T < 12; ++T)
            acc[T] += s_ag[ln][T * 33 + f] * w;
    }
    #pragma unroll
    for (int T = 0; T < 12; ++T)
        g_h0[(c * TT + T) * 64 + col] = fmaxf(acc[T], 0.f);
}

// ---------- aggregate h0 (N,T,64) -> (N,T,64) ----------
__global__ void k_agg_h(){
    int c   = blockIdx.x;
    int off = g_off[c], len = g_cnt[c];
    float dc = g_dis[c];
    int t = threadIdx.x;
    int cb = c * 768;
    float a0 = dc * g_h0[cb + t];
    float a1 = dc * g_h0[cb + t + 256];
    float a2 = dc * g_h0[cb + t + 512];
    for (int e = 0; e < len; ++e){
        int r = g_src[off + e];
        float dr = g_dis[r];
        int rb = r * 768;
        a0 += dr * g_h0[rb + t];
        a1 += dr * g_h0[rb + t + 256];
        a2 += dr * g_h0[rb + t + 512];
    }
    g_agg1[cb + t]       = dc * a0;
    g_agg1[cb + t + 256] = dc * a1;
    g_agg1[cb + t + 512] = dc * a2;
}

// ---------- fused GCN layer 1 (FFMA2) + LSTM-0 input projection ----------
#define GX_SMEM (25152 * 4)
__global__ __launch_bounds__(256)
void k_gcn1x(const float* __restrict__ W1, const float* __restrict__ b1,
             const float* __restrict__ wih, const float* __restrict__ bih,
             const float* __restrict__ bhh){
    extern __shared__ float sm[];
    float* A_s  = sm;             // 64 x 98  (agg1 tile, [k][n])
    float* W1_s = sm + 6272;      // 64 x 64
    float* b1_s = sm + 10368;     // 64
    float* A2_s = sm + 10432;     // 64 x 98  (h1 tile, [col][n])
    float* Wi_s = sm + 16704;     // 128 x 65
    float* bb_s = sm + 25024;     // 128
    int t  = threadIdx.x;
    int nb = blockIdx.x * 96;
    int jj = t & 31, pg = t >> 5;

    for (int idx = t; idx < 4096; idx += 256) W1_s[idx] = W1[idx];
    if (t < 64) b1_s[t] = b1[t];
    for (int idx = t; idx < 96 * 64; idx += 256){
        int n = idx >> 6, k = idx & 63;
        A_s[k * 98 + n] = g_agg1[(nb + n) * 64 + k];
    }
    __syncthreads();

    {   // GEMM1: 96 x 64
        ull acc[6][2];
        #pragma unroll
        for (int p = 0; p < 6; ++p){ acc[p][0] = 0ull; acc[p][1] = 0ull; }
        #pragma unroll 8
        for (int k = 0; k < 64; ++k){
            float w0 = W1_s[k * 64 + jj], w1 = W1_s[k * 64 + jj + 32];
            ull W0 = pack2(w0, w0), W1v = pack2(w1, w1);
            const float* Ar = &A_s[k * 98 + pg * 12];
            #pragma unroll
            for (int p = 0; p < 6; ++p){
                ull a = *(const ull*)(Ar + 2 * p);
                acc[p][0] = ffma2(a, W0, acc[p][0]);
                acc[p][1] = ffma2(a, W1v, acc[p][1]);
            }
        }
        float bb0 = b1_s[jj], bb1 = b1_s[jj + 32];
        #pragma unroll
        for (int p = 0; p < 6; ++p){
            float v0l, v0h, v1l, v1h;
            unpack2(acc[p][0], v0l, v0h);
            unpack2(acc[p][1], v1l, v1h);
            int n0 = pg * 12 + 2 * p;
            A2_s[jj * 98 + n0]            = fmaxf(v0l + bb0, 0.f);
            A2_s[jj * 98 + n0 + 1]        = fmaxf(v0h + bb0, 0.f);
            A2_s[(jj + 32) * 98 + n0]     = fmaxf(v1l + bb1, 0.f);
            A2_s[(jj + 32) * 98 + n0 + 1] = fmaxf(v1h + bb1, 0.f);
        }
    }
    __syncthreads();

    for (int half = 0; half < 2; ++half){
        for (int idx = t; idx < 128 * 64; idx += 256){
            int r = idx >> 6, k = idx & 63;
            int grow = (r >> 5) * 64 + half * 32 + (r & 31);
            Wi_s[r * 65 + k] = wih[grow * 64 + k];
        }
        if (t < 128){
            int grow = (t >> 5) * 64 + half * 32 + (t & 31);
            bb_s[t] = bih[grow] + bhh[grow];
        }
        __syncthreads();

        ull acc2[6][4];
        #pragma unroll
        for (int p = 0; p < 6; ++p)
            #pragma unroll
            for (int g = 0; g < 4; ++g) acc2[p][g] = 0ull;

        #pragma unroll 4
        for (int k = 0; k < 64; ++k){
            const float* Ar = &A2_s[k * 98 + pg * 12];
            ull a0 = *(const ull*)(Ar + 0);
            ull a1 = *(const ull*)(Ar + 2);
            ull a2 = *(const ull*)(Ar + 4);
            ull a3 = *(const ull*)(Ar + 6);
            ull a4 = *(const ull*)(Ar + 8);
            ull a5 = *(const ull*)(Ar + 10);
            #pragma unroll
            for (int g = 0; g < 4; ++g){
                float w = Wi_s[(g * 32 + jj) * 65 + k];
                ull W2 = pack2(w, w);
                acc2[0][g] = ffma2(a0, W2, acc2[0][g]);
                acc2[1][g] = ffma2(a1, W2, acc2[1][g]);
                acc2[2][g] = ffma2(a2, W2, acc2[2][g]);
                acc2[3][g] = ffma2(a3, W2, acc2[3][g]);
                acc2[4][g] = ffma2(a4, W2, acc2[4][g]);
                acc2[5][g] = ffma2(a5, W2, acc2[5][g]);
            }
        }
        float bi = bb_s[jj], bf = bb_s[32 + jj], bg = bb_s[64 + jj], bo = bb_s[96 + jj];
        int hcol = half * 32 + jj;
        #pragma unroll
        for (int p = 0; p < 6; ++p){
            float i0, i1, f0, f1, g0, g1, o0, o1;
            unpack2(acc2[p][0], i0, i1);
            unpack2(acc2[p][1], f0, f1);
            unpack2(acc2[p][2], g0, g1);
            unpack2(acc2[p][3], o0, o1);
            int row = nb + pg * 12 + 2 * p;
            ((float4*)g_pre)[row * 64 + hcol]       = make_float4(i0 + bi, f0 + bf, g0 + bg, o0 + bo);
            ((float4*)g_pre)[(row + 1) * 64 + hcol] = make_float4(i1 + bi, f1 + bf, g1 + bg, o1 + bo);
        }
        __syncthreads();
    }
}

// ---------- LSTM-1 input projection: g_pre = g_hs0 @ Wih1^T + bias ----------
#define XP_SMEM (14720 * 4)
__global__ __launch_bounds__(256)
void k_xproj2(const float* __restrict__ wih, const float* __restrict__ bih,
              const float* __restrict__ bhh){
    extern __shared__ float sm[];
    float* A_s  = sm;            // 64 x 98
    float* Wi_s = sm + 6272;     // 128 x 65
    float* bb_s = sm + 14592;    // 128
    int t  = threadIdx.x;
    int nb = blockIdx.x * 96;
    int cb = blockIdx.y * 32;
    int jj = t & 31, pg = t >> 5;

    for (int idx = t; idx < 128 * 64; idx += 256){
        int r = idx >> 6, k = idx & 63;
        int grow = (r >> 5) * 64 + cb + (r & 31);
        Wi_s[r * 65 + k] = wih[grow * 64 + k];
    }
    if (t < 128){
        int grow = (t >> 5) * 64 + cb + (t & 31);
        bb_s[t] = bih[grow] + bhh[grow];
    }
    for (int idx = t; idx < 96 * 64; idx += 256){
        int n = idx >> 6, k = idx & 63;
        A_s[k * 98 + n] = g_hs0[(nb + n) * 64 + k];
    }
    __syncthreads();

    ull acc2[6][4];
    #pragma unroll
    for (int p = 0; p < 6; ++p)
        #pragma unroll
        for (int g = 0; g < 4; ++g) acc2[p][g] = 0ull;

    #pragma unroll 4
    for (int k = 0; k < 64; ++k){
        const float* Ar = &A_s[k * 98 + pg * 12];
        ull a0 = *(const ull*)(Ar + 0);
        ull a1 = *(const ull*)(Ar + 2);
        ull a2 = *(const ull*)(Ar + 4);
        ull a3 = *(const ull*)(Ar + 6);
        ull a4 = *(const ull*)(Ar + 8);
        ull a5 = *(const ull*)(Ar + 10);
        #pragma unroll
        for (int g = 0; g < 4; ++g){
            float w = Wi_s[(g * 32 + jj) * 65 + k];
            ull W2 = pack2(w, w);
            acc2[0][g] = ffma2(a0, W2, acc2[0][g]);
            acc2[1][g] = ffma2(a1, W2, acc2[1][g]);
            acc2[2][g] = ffma2(a2, W2, acc2[2][g]);
            acc2[3][g] = ffma2(a3, W2, acc2[3][g]);
            acc2[4][g] = ffma2(a4, W2, acc2[4][g]);
            acc2[5][g] = ffma2(a5, W2, acc2[5][g]);
        }
    }
    float bi = bb_s[jj], bf = bb_s[32 + jj], bg = bb_s[64 + jj], bo = bb_s[96 + jj];
    int hcol = cb + jj;
    #pragma unroll
    for (int p = 0; p < 6; ++p){
        float i0, i1, f0, f1, g0, g1, o0, o1;
        unpack2(acc2[p][0], i0, i1);
        unpack2(acc2[p][1], f0, f1);
        unpack2(acc2[p][2], g0, g1);
        unpack2(acc2[p][3], o0, o1);
        int row = nb + pg * 12 + 2 * p;
        ((float4*)g_pre)[row * 64 + hcol]       = make_float4(i0 + bi, f0 + bf, g0 + bg, o0 + bo);
        ((float4*)g_pre)[(row + 1) * 64 + hcol] = make_float4(i1 + bi, f1 + bf, g1 + bg, o1 + bo);
    }
}

// ---------- persistent per-layer LSTM: 125 blocks x 80 nodes, 12 steps ----------
// layer 1 additionally computes the final FC in its epilogue.
// g_pre for step st is prefetched into registers BEFORE the GEMM so the
// scattered LDG.128 latency drains under the ~10k-cycle FFMA2 loop.
#define LSTM_SMEM ((256 * 65 + 64 * 82 + 64 * 82) * 4)

__global__ __launch_bounds__(256, 1)
void k_lstm_layer(int layer, const float* __restrict__ whh,
                  const float* __restrict__ fcw, const float* __restrict__ fcb,
                  float* __restrict__ out){
    extern __shared__ float smem[];
    float* W_s = smem;                 // [c 0..255][kk 0..63], pitch 65
    float* h_s = smem + 256 * 65;      // [hcol 0..63][n 0..79], pitch 82
    float* c_s = h_s + 64 * 82;

    int t  = threadIdx.x;
    int jj = t & 31, wg = t >> 5;
    int nb = blockIdx.x * 80;

    for (int idx = t; idx < 256 * 64; idx += 256){
        int k = idx & 63, c = idx >> 6;
        W_s[c * 65 + k] = whh[idx];
    }
    for (int idx = t; idx < 64 * 82; idx += 256){
        h_s[idx] = 0.f;
        c_s[idx] = 0.f;
    }
    __syncthreads();

    for (int st = 0; st < TT; ++st){
        // prefetch this step's pre-activations (independent of h)
        float4 pv[5][2][2];
        #pragma unroll
        for (int p = 0; p < 5; ++p)
            #pragma unroll
            for (int hs2 = 0; hs2 < 2; ++hs2)
                #pragma unroll
                for (int half = 0; half < 2; ++half){
                    int nloc = wg * 10 + 2 * p + half;
                    int hcol = jj + 32 * hs2;
                    pv[p][hs2][half] =
                        ((const float4*)g_pre)[((nb + nloc) * TT + st) * 64 + hcol];
                }

        ull acc[8][5];
        #pragma unroll
        for (int g = 0; g < 8; ++g)
            #pragma unroll
            for (int p = 0; p < 5; ++p) acc[g][p] = 0ull;

        #pragma unroll 4
        for (int kk = 0; kk < 64; ++kk){
            const float* Ar = h_s + kk * 82 + wg * 10;
            ull a0 = *(const ull*)(Ar + 0);
            ull a1 = *(const ull*)(Ar + 2);
            ull a2 = *(const ull*)(Ar + 4);
            ull a3 = *(const ull*)(Ar + 6);
            ull a4 = *(const ull*)(Ar + 8);
            #pragma unroll
            for (int g = 0; g < 8; ++g){
                float w = W_s[(jj + 32 * g) * 65 + kk];
                ull W2 = pack2(w, w);
                acc[g][0] = ffma2(a0, W2, acc[g][0]);
                acc[g][1] = ffma2(a1, W2, acc[g][1]);
                acc[g][2] = ffma2(a2, W2, acc[g][2]);
                acc[g][3] = ffma2(a3, W2, acc[g][3]);
                acc[g][4] = ffma2(a4, W2, acc[g][4]);
            }
        }
        __syncthreads();

        #pragma unroll
        for (int p = 0; p < 5; ++p){
            #pragma unroll
            for (int hs2 = 0; hs2 < 2; ++hs2){
                int hcol = jj + 32 * hs2;
                float i0, i1, f0, f1, g0, g1, o0, o1;
                unpack2(acc[0 + hs2][p], i0, i1);
                unpack2(acc[2 + hs2][p], f0, f1);
                unpack2(acc[4 + hs2][p], g0, g1);
                unpack2(acc[6 + hs2][p], o0, o1);
                #pragma unroll
                for (int half = 0; half < 2; ++half){
                    int nloc = wg * 10 + 2 * p + half;
                    int node = nb + nloc;
                    float4 pvv = pv[p][hs2][half];
                    float iv = (half ? i1 : i0) + pvv.x;
                    float fv = (half ? f1 : f0) + pvv.y;
                    float gv = (half ? g1 : g0) + pvv.z;
                    float ov = (half ? o1 : o0) + pvv.w;
                    float cold = c_s[hcol * 82 + nloc];
                    float cn = fsig(fv) * cold + fsig(iv) * tanha(gv);
                    float hn = fsig(ov) * tanha(cn);
                    c_s[hcol * 82 + nloc] = cn;
                    h_s[hcol * 82 + nloc] = hn;
                    if (layer == 0)
                        g_hs0[(node * TT + st) * 64 + hcol] = hn;
                }
            }
        }
        __syncthreads();
    }

    if (layer == 1){
        // fused FC on final h (already in smem); reuse W_s for fc_w^T
        for (int idx = t; idx < 1024; idx += 256){
            int k = idx >> 4, o = idx & 15;
            W_s[k * 16 + o] = fcw[o * 64 + k];
        }
        __syncthreads();
        #pragma unroll
        for (int q = 0; q < 5; ++q){
            int oi = t + 256 * q;              // 80 nodes x 16 outs
            int nloc = oi >> 4, o = oi & 15;
            float acc = fcb[o];
            #pragma unroll 8
            for (int k = 0; k < 64; ++k)
                acc += h_s[k * 82 + nloc] * W_s[k * 16 + o];
            out[(nb + nloc) * 16 + o] = acc;
        }
    }
}

extern "C" void kernel_launch(void* const* d_in, const int* in_sizes, int n_in,
                              void* d_out, int out_size){
    const float* x    = (const float*)d_in[0];
    const void*  ei   =               d_in[1];
    const float* gw0  = (const float*)d_in[2];
    const float* gb0  = (const float*)d_in[3];
    const float* gw1  = (const float*)d_in[4];
    const float* gb1  = (const float*)d_in[5];
    const float* wih0 = (const float*)d_in[6];
    const float* whh0 = (const float*)d_in[7];
    const float* bih0 = (const float*)d_in[8];
    const float* bhh0 = (const float*)d_in[9];
    const float* wih1 = (const float*)d_in[10];
    const float* whh1 = (const float*)d_in[11];
    const float* bih1 = (const float*)d_in[12];
    const float* bhh1 = (const float*)d_in[13];
    const float* fcw  = (const float*)d_in[14];
    const float* fcb  = (const float*)d_in[15];
    float* out = (float*)d_out;

    cudaFuncSetAttribute(k_lstm_layer, cudaFuncAttributeMaxDynamicSharedMemorySize, LSTM_SMEM);
    cudaFuncSetAttribute(k_gcn1x,      cudaFuncAttributeMaxDynamicSharedMemorySize, GX_SMEM);
    cudaFuncSetAttribute(k_xproj2,     cudaFuncAttributeMaxDynamicSharedMemorySize, XP_SMEM);

    // CSR build
    k_init <<<40, 256>>>((const int*)ei);
    k_count<<<(NE + 255) / 256, 256>>>(ei);
    k_scan1<<<79, 128>>>();
    k_scan3<<<79, 128>>>();
    k_fill <<<(NE + 255) / 256, 256>>>(ei);

    // GCN layer 0 (aggregation + GEMM fused; 4 nodes/block)
    k_aggx_gcn0<<<2500, 256>>>(x, gw0, gb0);
    // GCN layer 1 fused with LSTM-0 input projection
    k_agg_h<<<NN, 256>>>();
    k_gcn1x<<<1250, 256, GX_SMEM>>>(gw1, gb1, wih0, bih0, bhh0);

    // LSTM layer 0
    k_lstm_layer<<<125, 256, LSTM_SMEM>>>(0, whh0, fcw, fcb, out);

    // LSTM layer 1 (FC fused into epilogue)
    {
        dim3 gx(1250, 2);
        k_xproj2<<<gx, 256, XP_SMEM>>>(wih1, bih1, bhh1);
    }
    k_lstm_layer<<<125, 256, LSTM_SMEM>>>(1, whh1, fcw, fcb, out);
}